// round 11
// baseline (speedup 1.0000x reference)
#include <cuda_runtime.h>
#include <stdint.h>

// ---------------------------------------------------------------------------
// Raindrop ObservationPropagation, use_beta=False, heads=1.
// Identity: segment softmax over gamma sums to exactly 1 and the message uses
// x[tgt] (constant within each segment), so
//   out[n] = relu(x[n] @ Wv + bv) * has_incoming_edge[n]
// edge_weights cancel. Work = edge-target mask scatter + masked 50000x96x96
// GEMM (bias+relu epilogue).
//
// R9: R8 was issue-bound (issue=47.1%, fma=31.8%, occ=16%). Halve the
// instruction stream with packed fma.rn.f32x2: 24 FFMA2 + 7 LDS + 3 MOV per
// warp-k instead of 48 FFMA + 7 LDS. Row-pairs come free from LDS.128 of the
// k-major tile; only 3 weight dups per k. 170-reg cap + unroll 2 keeps the
// R3 spill failure mode impossible (~100 live regs).
// ---------------------------------------------------------------------------

#define DIM 96
#define RPB 64            // rows per block (4 warps x 16 rows)
#define SXT_S 68          // tile stride: lane k-stride = 68 words = 4 banks -> 0 conflicts
#define MAX_NODES (1 << 16)

__device__ unsigned char g_mask[MAX_NODES];   // zero-initialized at module load

// mask[tgt[e]] = 1; 4 edges/thread. Per-block width detection: warp 0 probes
// the first 32 64-bit words (source row; in-bounds under both widths):
// int64 -> values in [0,n); int32 -> packed pair >= 2^32 almost surely.
__global__ void rd_scatter_kernel(const void* __restrict__ ei,
                                  long long E, int n_nodes) {
    __shared__ int s_is64;
    const int tid = threadIdx.x;
    if (tid < 32) {
        long long v = ((const long long*)ei)[tid];
        bool bad = (v < 0 || v >= (long long)n_nodes);
        unsigned b = __ballot_sync(0xffffffffu, bad);
        if (tid == 0) s_is64 = (b == 0);
    }
    __syncthreads();
    const bool is64 = s_is64;

    long long q = (long long)blockIdx.x * blockDim.x + tid;  // quad index
    long long e = q * 4;
    if (e >= E) return;
    long long t[4];
    int cnt;
    if (e + 4 <= E) {
        cnt = 4;
        if (is64) {
            const longlong2* tp = (const longlong2*)((const long long*)ei + E);
            longlong2 v0 = tp[q * 2];
            longlong2 v1 = tp[q * 2 + 1];
            t[0] = v0.x; t[1] = v0.y; t[2] = v1.x; t[3] = v1.y;
        } else {
            const int4* tp = (const int4*)((const int*)ei + E);
            int4 v = tp[q];
            t[0] = v.x; t[1] = v.y; t[2] = v.z; t[3] = v.w;
        }
    } else {
        cnt = (int)(E - e);
        for (int i = 0; i < cnt; i++) {
            if (is64) t[i] = ((const long long*)ei)[E + e + i];
            else      t[i] = (long long)((const int*)ei)[E + e + i];
        }
    }
#pragma unroll
    for (int i = 0; i < 4; i++) {
        if (i < cnt && t[i] >= 0 && t[i] < (long long)n_nodes)
            g_mask[t[i]] = 1;           // idempotent unconditional byte store
    }
}

// packed fp32x2 fma: d = a*b + d (elementwise on the 2 packed floats)
#define FMA2(d, a, b) asm("fma.rn.f32x2 %0, %1, %2, %3;" \
                          : "=l"(d) : "l"(a), "l"(b), "l"(d))

// out[n] = mask[n] * relu(x[n] @ Wv + bv)
// Block 128 = 4 warps, 64 rows. Warp w owns rows [16w,16w+16) as 8 row-PAIRS;
// lane tx owns cols {tx, tx+32, tx+64}. x tile k-major sXT[k][row], stride 68
// (STS transpose + broadcast LDS.128 conflict-free). Consecutive rows in the
// tile land in one LDS.128 as 2 natural f32x2 pairs -> no x duplication.
// Per warp-k: 4 LDS.128 + 3 LDS.32 + 3 dup-MOV + 24 FFMA2 (96 FMA lanes).
__global__ __launch_bounds__(128, 3)
void rd_gemm_kernel(const float* __restrict__ x,
                    const float* __restrict__ Wv,
                    const float* __restrict__ bv,
                    float* __restrict__ out, int n) {
    __shared__ float sW[DIM * DIM];                     // 36864 B
    __shared__ float sB[DIM];
    __shared__ __align__(16) float sXT[DIM][SXT_S];     // 26112 B

    const int tid  = threadIdx.x;
    const int row0 = blockIdx.x * RPB;

    // Wv: 2304 float4, 18 per thread.
    {
        const float4* W4 = (const float4*)Wv;
        float4* sW4 = (float4*)sW;
#pragma unroll
        for (int i = 0; i < 18; i++) sW4[tid + 128 * i] = W4[tid + 128 * i];
    }
    if (tid < DIM) sB[tid] = bv[tid];

    // Conflict-free transposed tile load: unit u = rg*96 + k (rg = row-group
    // of 4). Thread gathers rows rg*4..rg*4+3 at column k (coalesced across
    // consecutive-k lanes), stores ONE STS.128 at sXT[k][rg*4].
    const bool full = (row0 + RPB <= n);
#pragma unroll
    for (int it = 0; it < 12; it++) {
        int u  = tid + 128 * it;        // 0..1535
        int rg = u / DIM;               // 0..15
        int k  = u - rg * DIM;          // 0..95
        int r  = row0 + rg * 4;
        float v0 = 0.f, v1 = 0.f, v2 = 0.f, v3 = 0.f;
        if (full) {
            v0 = x[(size_t)(r + 0) * DIM + k];
            v1 = x[(size_t)(r + 1) * DIM + k];
            v2 = x[(size_t)(r + 2) * DIM + k];
            v3 = x[(size_t)(r + 3) * DIM + k];
        } else {
            if (r + 0 < n) v0 = x[(size_t)(r + 0) * DIM + k];
            if (r + 1 < n) v1 = x[(size_t)(r + 1) * DIM + k];
            if (r + 2 < n) v2 = x[(size_t)(r + 2) * DIM + k];
            if (r + 3 < n) v3 = x[(size_t)(r + 3) * DIM + k];
        }
        *(float4*)&sXT[k][rg * 4] = make_float4(v0, v1, v2, v3);
    }
    __syncthreads();

    const int tx = tid & 31;
    const int wr = (tid >> 5) * 16;     // first of this warp's 16 rows

    // 8 row-pairs x 3 col-groups, packed f32x2 accumulators (48 regs).
    unsigned long long ac0[8], ac1[8], ac2[8];
#pragma unroll
    for (int p = 0; p < 8; p++) { ac0[p] = 0ull; ac1[p] = 0ull; ac2[p] = 0ull; }

#pragma unroll 2
    for (int k = 0; k < DIM; k++) {
        // 16 rows = 8 f32x2 pairs via 4 broadcast LDS.128 (wr%16==0 -> aligned)
        ulonglong2 xa = *(const ulonglong2*)&sXT[k][wr];        // pairs 0,1
        ulonglong2 xb = *(const ulonglong2*)&sXT[k][wr + 4];    // pairs 2,3
        ulonglong2 xc = *(const ulonglong2*)&sXT[k][wr + 8];    // pairs 4,5
        ulonglong2 xd = *(const ulonglong2*)&sXT[k][wr + 12];   // pairs 6,7
        unsigned int w0 = __float_as_uint(sW[k * DIM + tx]);
        unsigned int w1 = __float_as_uint(sW[k * DIM + tx + 32]);
        unsigned int w2 = __float_as_uint(sW[k * DIM + tx + 64]);
        unsigned long long wd0, wd1, wd2;
        asm("mov.b64 %0, {%1, %1};" : "=l"(wd0) : "r"(w0));
        asm("mov.b64 %0, {%1, %1};" : "=l"(wd1) : "r"(w1));
        asm("mov.b64 %0, {%1, %1};" : "=l"(wd2) : "r"(w2));
        FMA2(ac0[0], xa.x, wd0); FMA2(ac1[0], xa.x, wd1); FMA2(ac2[0], xa.x, wd2);
        FMA2(ac0[1], xa.y, wd0); FMA2(ac1[1], xa.y, wd1); FMA2(ac2[1], xa.y, wd2);
        FMA2(ac0[2], xb.x, wd0); FMA2(ac1[2], xb.x, wd1); FMA2(ac2[2], xb.x, wd2);
        FMA2(ac0[3], xb.y, wd0); FMA2(ac1[3], xb.y, wd1); FMA2(ac2[3], xb.y, wd2);
        FMA2(ac0[4], xc.x, wd0); FMA2(ac1[4], xc.x, wd1); FMA2(ac2[4], xc.x, wd2);
        FMA2(ac0[5], xc.y, wd0); FMA2(ac1[5], xc.y, wd1); FMA2(ac2[5], xc.y, wd2);
        FMA2(ac0[6], xd.x, wd0); FMA2(ac1[6], xd.x, wd1); FMA2(ac2[6], xd.x, wd2);
        FMA2(ac0[7], xd.y, wd0); FMA2(ac1[7], xd.y, wd1); FMA2(ac2[7], xd.y, wd2);
    }

    const float b0 = sB[tx];
    const float b1 = sB[tx + 32];
    const float b2 = sB[tx + 64];

#pragma unroll
    for (int p = 0; p < 8; p++) {
        unsigned int lo0, hi0, lo1, hi1, lo2, hi2;
        asm("mov.b64 {%0, %1}, %2;" : "=r"(lo0), "=r"(hi0) : "l"(ac0[p]));
        asm("mov.b64 {%0, %1}, %2;" : "=r"(lo1), "=r"(hi1) : "l"(ac1[p]));
        asm("mov.b64 {%0, %1}, %2;" : "=r"(lo2), "=r"(hi2) : "l"(ac2[p]));
        float v0[2] = {__uint_as_float(lo0), __uint_as_float(hi0)};
        float v1[2] = {__uint_as_float(lo1), __uint_as_float(hi1)};
        float v2[2] = {__uint_as_float(lo2), __uint_as_float(hi2)};
#pragma unroll
        for (int h = 0; h < 2; h++) {
            int r = row0 + wr + 2 * p + h;
            if (r < n) {
                float m = g_mask[r] ? 1.f : 0.f;
                float* o = out + (size_t)r * DIM;
                o[tx]      = fmaxf(v0[h] + b0, 0.f) * m;
                o[tx + 32] = fmaxf(v1[h] + b1, 0.f) * m;
                o[tx + 64] = fmaxf(v2[h] + b2, 0.f) * m;
            }
        }
    }
}

extern "C" void kernel_launch(void* const* d_in, const int* in_sizes, int n_in,
                              void* d_out, int out_size) {
    const float* x  = (const float*)d_in[0];
    // d_in[1] = p_t (unused, use_beta=False)
    const float* Wv = (const float*)d_in[2];
    const float* bv = (const float*)d_in[3];
    // d_in[4] = edge_weights (cancels: segment softmax sums to 1)
    const void*  ei = d_in[5];

    const int n = in_sizes[0] / DIM;                 // 50000
    const long long E = (long long)in_sizes[5] / 2;  // 800000

    {   // 1) fused detect + scatter (4 edges/thread)
        long long quads = (E + 3) / 4;
        int threads = 256;
        int blocks = (int)((quads + threads - 1) / threads);
        rd_scatter_kernel<<<blocks, threads>>>(ei, E, n);
    }
    {   // 2) masked GEMM + bias + relu
        int blocks = (n + RPB - 1) / RPB;
        rd_gemm_kernel<<<blocks, 128>>>(x, Wv, bv, (float*)d_out, n);
    }
}